// round 4
// baseline (speedup 1.0000x reference)
#include <cuda_runtime.h>
#include <cstdint>
#include <cstdio>

// ---------------------------------------------------------------------------
// GraphFusionLayerAtt: fully-fused fp32 pipeline.
//   B=65536 batch elements, H=256.
//   Per batch element b (identity GAT path, valid for all b >= 1):
//     xa = relu(audio[b] @ W_pa + b_pa)
//     xt = relu(text[b]  @ W_pt + b_pt)
//     y1a = relu(xa @ W_g1 + b_g1)   (512)
//     y1t = relu(xt @ W_g1 + b_g1)   (512)
//     y2a = y1a @ W_g2 + b_g2        (256)
//     y2t = y1t @ W_g2 + b_g2        (256)
//     s?  = y2? . W_af + b_af ; w = softmax([sa,st])
//     fused = wa*y2a + wt*y2t
//     out[b] = fused @ W_fc + b_fc
//   Batch element 0 (graph nodes 0,1) does real 2x2 GAT attention at both
//   layers -> handled by a dedicated fixup kernel that overwrites out[0].
// ---------------------------------------------------------------------------

typedef unsigned long long u64;

__device__ __forceinline__ u64 pack2(float x, float y) {
    u64 r; asm("mov.b64 %0, {%1, %2};" : "=l"(r) : "f"(x), "f"(y)); return r;
}
__device__ __forceinline__ u64 fma2(u64 a, u64 b, u64 c) {
    u64 d; asm("fma.rn.f32x2 %0, %1, %2, %3;" : "=l"(d) : "l"(a), "l"(b), "l"(c)); return d;
}
__device__ __forceinline__ float2 unpk(u64 v) {
    float2 f; asm("mov.b64 {%0, %1}, %2;" : "=f"(f.x), "=f"(f.y) : "l"(v)); return f;
}

static constexpr int H      = 256;
static constexpr int MB     = 32;     // batch elements per CTA
static constexpr int NTHR   = 256;
static constexpr int KT     = 16;     // k-tile for weight staging

// smem layout (floats)
static constexpr int OFF_Y1 = 0;          // 64x512 = 32768  (also: stage-1 inputs, fused)
static constexpr int OFF_ND = 32768;      // 64x256 = 16384  (nodes, later y2)
static constexpr int OFF_W  = 49152;      // 2 x 16x256 = 8192 (W double buffer)
static constexpr int OFF_S  = 57344;      // 64 scores
static constexpr int OFF_WT = 57408;      // 64 softmax weights
static constexpr int SMEM_FLOATS = 57472;
static constexpr int SMEM_BYTES  = SMEM_FLOATS * 4;   // 229,888 B

// cooperative load of a 16 x 256 weight tile (as float4s) ---------------------
__device__ __forceinline__ void ldgW(float4* pref, const float* __restrict__ gW,
                                     int ldw, int n0, int k0) {
    const int tid = threadIdx.x;
#pragma unroll
    for (int j = 0; j < 4; j++) {
        int f  = tid + (j << 8);          // 0..1023
        int kk = f >> 6;                  // 0..15
        int n  = (f & 63) << 2;           // 0..252
        pref[j] = *(const float4*)(gW + (size_t)(k0 + kk) * ldw + n0 + n);
    }
}
__device__ __forceinline__ void stsW(float* sW, const float4* pref) {
    const int tid = threadIdx.x;
#pragma unroll
    for (int j = 0; j < 4; j++) {
        int f  = tid + (j << 8);
        int kk = f >> 6;
        int n  = (f & 63) << 2;
        *(float4*)(sW + kk * 256 + n) = pref[j];
    }
}

// One GEMM stage: Y[r, n0..n0+256) = act( X[r,:] @ W[:, n0..n0+256) + b )
//   X in smem (ldx), W/b in global (L2-resident), Y smem or global.
//   Rows of this stage: 8 warps x TM rows.  Output row = rowBase + r*rowStride.
// Inner loop: f32x2 packed FMA, W tiles double-buffered through smem.
template <int TM, bool RELU>
__device__ __forceinline__ void gemm_tile(
    const float* __restrict__ sX, int ldx, int K,
    const float* __restrict__ gW, int ldw, int n0,
    const float* __restrict__ gB,
    float* __restrict__ Y, int ldy, int rowStride, int rowBase,
    float* __restrict__ sW)
{
    const int tid  = threadIdx.x;
    const int ty   = tid >> 5;
    const int tx   = tid & 31;
    const int rb   = ty * TM;
    const int ncol = tx << 3;             // 8 cols per thread

    // init accumulators with bias
    float4 bb0 = *(const float4*)(gB + n0 + ncol);
    float4 bb1 = *(const float4*)(gB + n0 + ncol + 4);
    u64 acc[TM][4];
    {
        u64 b0 = pack2(bb0.x, bb0.y), b1 = pack2(bb0.z, bb0.w);
        u64 b2 = pack2(bb1.x, bb1.y), b3 = pack2(bb1.z, bb1.w);
#pragma unroll
        for (int i = 0; i < TM; i++) { acc[i][0]=b0; acc[i][1]=b1; acc[i][2]=b2; acc[i][3]=b3; }
    }

    const int NT = K >> 4;
    float4 pref[4];
    ldgW(pref, gW, ldw, n0, 0);
    stsW(sW, pref);                          // tile 0 -> buf 0
    if (NT > 1) ldgW(pref, gW, ldw, n0, KT); // tile 1 -> regs
    __syncthreads();

    for (int kt = 0; kt < NT; kt++) {
        const float* sWc = sW + ((kt & 1) ? 4096 : 0);
        const float* sXk = sX + (kt << 4);
#pragma unroll
        for (int kk = 0; kk < KT; kk += 4) {
            float4 xv[TM];
#pragma unroll
            for (int i = 0; i < TM; i++)
                xv[i] = *(const float4*)(sXk + (rb + i) * ldx + kk);
#pragma unroll
            for (int dk = 0; dk < 4; dk++) {
                const float* wr = sWc + ((kk + dk) << 8) + ncol;
                ulonglong2 wA = *(const ulonglong2*)(wr);
                ulonglong2 wB = *(const ulonglong2*)(wr + 4);
#pragma unroll
                for (int i = 0; i < TM; i++) {
                    float xs = (dk == 0) ? xv[i].x : (dk == 1) ? xv[i].y
                             : (dk == 2) ? xv[i].z : xv[i].w;
                    u64 xb = pack2(xs, xs);
                    acc[i][0] = fma2(xb, wA.x, acc[i][0]);
                    acc[i][1] = fma2(xb, wA.y, acc[i][1]);
                    acc[i][2] = fma2(xb, wB.x, acc[i][2]);
                    acc[i][3] = fma2(xb, wB.y, acc[i][3]);
                }
            }
        }
        if (kt + 1 < NT) {
            stsW(sW + (((kt + 1) & 1) ? 4096 : 0), pref);
            if (kt + 2 < NT) ldgW(pref, gW, ldw, n0, (kt + 2) << 4);
        }
        __syncthreads();
    }

    // epilogue
#pragma unroll
    for (int i = 0; i < TM; i++) {
        int row = rowBase + (rb + i) * rowStride;
        float2 p0 = unpk(acc[i][0]), p1 = unpk(acc[i][1]);
        float2 p2 = unpk(acc[i][2]), p3 = unpk(acc[i][3]);
        if (RELU) {
            p0.x = fmaxf(p0.x, 0.f); p0.y = fmaxf(p0.y, 0.f);
            p1.x = fmaxf(p1.x, 0.f); p1.y = fmaxf(p1.y, 0.f);
            p2.x = fmaxf(p2.x, 0.f); p2.y = fmaxf(p2.y, 0.f);
            p3.x = fmaxf(p3.x, 0.f); p3.y = fmaxf(p3.y, 0.f);
        }
        float4 o0 = make_float4(p0.x, p0.y, p1.x, p1.y);
        float4 o1 = make_float4(p2.x, p2.y, p3.x, p3.y);
        *(float4*)(Y + (size_t)row * ldy + n0 + ncol)     = o0;
        *(float4*)(Y + (size_t)row * ldy + n0 + ncol + 4) = o1;
    }
}

// ---------------------------------------------------------------------------
__global__ void __launch_bounds__(NTHR, 1)
fused_main(const float* __restrict__ audio, const float* __restrict__ text,
           const float* __restrict__ W_pa, const float* __restrict__ b_pa,
           const float* __restrict__ W_pt, const float* __restrict__ b_pt,
           const float* __restrict__ W_g1, const float* __restrict__ b_g1,
           const float* __restrict__ W_g2, const float* __restrict__ b_g2,
           const float* __restrict__ W_af, const float* __restrict__ b_af,
           const float* __restrict__ W_fc, const float* __restrict__ b_fc,
           float* __restrict__ out)
{
    extern __shared__ float smem[];
    float* sY1 = smem + OFF_Y1;
    float* sND = smem + OFF_ND;
    float* sW  = smem + OFF_W;
    float* sS  = smem + OFF_S;
    float* sWt = smem + OFF_WT;

    const int tid = threadIdx.x;
    const int b0  = blockIdx.x * MB;

    // stage 0: stage input tiles (audio -> sY1[0:8192), text -> sY1[8192:16384))
    {
        const float4* gA = (const float4*)(audio + (size_t)b0 * H);
        const float4* gT = (const float4*)(text  + (size_t)b0 * H);
        float4* sA = (float4*)sY1;
        float4* sT = (float4*)(sY1 + 8192);
#pragma unroll
        for (int j = 0; j < 8; j++) { int f = tid + (j << 8); sA[f] = gA[f]; sT[f] = gT[f]; }
    }
    // (gemm prologue __syncthreads orders the stores above before any read)

    // stage 1: projections -> interleaved node rows in sND
    gemm_tile<4, true >(sY1,        256, 256, W_pa, 256, 0,   b_pa, sND, 256, 2, 0, sW);
    gemm_tile<4, true >(sY1 + 8192, 256, 256, W_pt, 256, 0,   b_pt, sND, 256, 2, 1, sW);
    // stage 2: GAT1 identity path, N=512 in two 256-col chunks -> sY1
    gemm_tile<8, true >(sND, 256, 256, W_g1, 512, 0,   b_g1, sY1, 512, 1, 0, sW);
    gemm_tile<8, true >(sND, 256, 256, W_g1, 512, 256, b_g1, sY1, 512, 1, 0, sW);
    // stage 3: GAT2 identity path (no relu) -> sND (y2)
    gemm_tile<8, false>(sY1, 512, 512, W_g2, 256, 0,   b_g2, sND, 256, 1, 0, sW);
    __syncthreads();

    // stage 4: attention scores s[r] = y2[r] . W_af + b_af  (warp per 8 rows)
    {
        const int wid = tid >> 5, lane = tid & 31;
#pragma unroll
        for (int rr = 0; rr < 8; rr++) {
            int r = wid * 8 + rr;
            const float* yr = sND + r * 256;
            float p = 0.f;
#pragma unroll
            for (int j = 0; j < 8; j++) p += yr[lane + (j << 5)] * W_af[lane + (j << 5)];
#pragma unroll
            for (int o = 16; o; o >>= 1) p += __shfl_xor_sync(0xffffffffu, p, o);
            if (lane == 0) sS[r] = p + b_af[0];
        }
    }
    __syncthreads();
    if (tid < MB) {
        float s0 = sS[2 * tid], s1 = sS[2 * tid + 1];
        float mx = fmaxf(s0, s1);
        float e0 = expf(s0 - mx), e1 = expf(s1 - mx);
        float inv = 1.f / (e0 + e1);
        sWt[2 * tid]     = e0 * inv;
        sWt[2 * tid + 1] = e1 * inv;
    }
    __syncthreads();

    // fuse: fused[m] = wa*y2[2m] + wt*y2[2m+1]  -> sY1 rows m (stride 256)
#pragma unroll
    for (int j = 0; j < 8; j++) {
        int f  = tid + (j << 8);          // float4 index, 0..2047
        int m  = f >> 6;                  // 64 float4 per row
        int n4 = f & 63;
        float wa = sWt[2 * m], wt = sWt[2 * m + 1];
        float4 va = ((const float4*)(sND + (2 * m) * 256))[n4];
        float4 vt = ((const float4*)(sND + (2 * m + 1) * 256))[n4];
        float4 o  = make_float4(wa * va.x + wt * vt.x, wa * va.y + wt * vt.y,
                                wa * va.z + wt * vt.z, wa * va.w + wt * vt.w);
        ((float4*)(sY1 + m * 256))[n4] = o;
    }
    // stage 5: output projection (gemm prologue sync covers the stores above)
    gemm_tile<4, false>(sY1, 256, 256, W_fc, 256, 0, b_fc,
                        out + (size_t)b0 * H, 256, 1, 0, sW);
}

// ---------------------------------------------------------------------------
// Batch 0 fixup: full 2x2 GAT attention for nodes {0,1}; overwrites out[0].
// ---------------------------------------------------------------------------
__device__ __forceinline__ float lrelu(float x) { return x > 0.f ? x : 0.2f * x; }

__global__ void fix_batch0(
    const float* __restrict__ audio, const float* __restrict__ text,
    const float* __restrict__ W_pa, const float* __restrict__ b_pa,
    const float* __restrict__ W_pt, const float* __restrict__ b_pt,
    const float* __restrict__ W_g1, const float* __restrict__ as1,
    const float* __restrict__ ad1, const float* __restrict__ b_g1,
    const float* __restrict__ W_g2, const float* __restrict__ as2,
    const float* __restrict__ ad2, const float* __restrict__ b_g2,
    const float* __restrict__ W_af, const float* __restrict__ b_af,
    const float* __restrict__ W_fc, const float* __restrict__ b_fc,
    float* __restrict__ out)
{
    __shared__ float a0[256], t0[256], x0[256], x1[256];
    __shared__ float xs1[2][512], y1[2][512];
    __shared__ float xs2[2][256], y2[2][256];
    __shared__ float sc[16];
    __shared__ float alpha1[2][2][2];   // [t][s][h]
    __shared__ float alpha2[2][2];      // [t][s]
    __shared__ float fw[2], fused[256];

    const int tid = threadIdx.x;
    const int wid = tid >> 5, lane = tid & 31;

    a0[tid] = audio[tid]; t0[tid] = text[tid];
    __syncthreads();

    // projections
    {
        float aa = b_pa[tid], at = b_pt[tid];
        for (int k = 0; k < 256; k++) {
            aa += a0[k] * W_pa[k * 256 + tid];
            at += t0[k] * W_pt[k * 256 + tid];
        }
        x0[tid] = fmaxf(aa, 0.f);
        x1[tid] = fmaxf(at, 0.f);
    }
    __syncthreads();

    // GAT1 projections: xs1[r][j] = x_r @ W_g1
    for (int idx = tid; idx < 1024; idx += 256) {
        int r = idx >> 9, j = idx & 511;
        const float* xr = r ? x1 : x0;
        float acc = 0.f;
        for (int k = 0; k < 256; k++) acc += xr[k] * W_g1[k * 512 + j];
        xs1[r][j] = acc;
    }
    __syncthreads();

    // e_src1/e_dst1 : 8 warp reductions. wid: r=bit0, h=bit1, dst=bit2
    {
        int r = wid & 1, h = (wid >> 1) & 1, isdst = wid >> 2;
        const float* av = isdst ? ad1 : as1;
        float p = 0.f;
        for (int c = lane; c < 256; c += 32) p += xs1[r][h * 256 + c] * av[h * 256 + c];
#pragma unroll
        for (int o = 16; o; o >>= 1) p += __shfl_xor_sync(0xffffffffu, p, o);
        if (lane == 0) sc[wid] = p;     // sc[(h<<1)|r] = e_src, sc[4+(h<<1)|r] = e_dst
    }
    __syncthreads();
    if (tid == 0) {
        for (int t = 0; t < 2; t++)
            for (int h = 0; h < 2; h++) {
                float l0 = lrelu(sc[(h << 1) | 0] + sc[4 + ((h << 1) | t)]);
                float l1 = lrelu(sc[(h << 1) | 1] + sc[4 + ((h << 1) | t)]);
                float mx = fmaxf(l0, l1);
                float e0 = expf(l0 - mx), e1 = expf(l1 - mx);
                float inv = 1.f / (e0 + e1);
                alpha1[t][0][h] = e0 * inv;
                alpha1[t][1][h] = e1 * inv;
            }
    }
    __syncthreads();
    // y1 = relu(agg + b_g1)
    for (int idx = tid; idx < 1024; idx += 256) {
        int t = idx >> 9, j = idx & 511, h = j >> 8;
        float v = alpha1[t][0][h] * xs1[0][j] + alpha1[t][1][h] * xs1[1][j] + b_g1[j];
        y1[t][j] = fmaxf(v, 0.f);
    }
    __syncthreads();

    // GAT2 projections
    for (int idx = tid; idx < 512; idx += 256) {
        int r = idx >> 8, j = idx & 255;
        float acc = 0.f;
        for (int k = 0; k < 512; k++) acc += y1[r][k] * W_g2[k * 256 + j];
        xs2[r][j] = acc;
    }
    __syncthreads();
    if (wid < 4) {
        int r = wid & 1, isdst = wid >> 1;
        const float* av = isdst ? ad2 : as2;
        float p = 0.f;
        for (int c = lane; c < 256; c += 32) p += xs2[r][c] * av[c];
#pragma unroll
        for (int o = 16; o; o >>= 1) p += __shfl_xor_sync(0xffffffffu, p, o);
        if (lane == 0) sc[8 + wid] = p;  // sc[8+r]=e_src2, sc[10+r]=e_dst2
    }
    __syncthreads();
    if (tid == 0) {
        for (int t = 0; t < 2; t++) {
            float l0 = lrelu(sc[8 + 0] + sc[10 + t]);
            float l1 = lrelu(sc[8 + 1] + sc[10 + t]);
            float mx = fmaxf(l0, l1);
            float e0 = expf(l0 - mx), e1 = expf(l1 - mx);
            float inv = 1.f / (e0 + e1);
            alpha2[t][0] = e0 * inv; alpha2[t][1] = e1 * inv;
        }
    }
    __syncthreads();
    // y2 (no relu)
    for (int idx = tid; idx < 512; idx += 256) {
        int t = idx >> 8, j = idx & 255;
        y2[t][j] = alpha2[t][0] * xs2[0][j] + alpha2[t][1] * xs2[1][j] + b_g2[j];
    }
    __syncthreads();
    if (wid < 2) {
        float p = 0.f;
        for (int c = lane; c < 256; c += 32) p += y2[wid][c] * W_af[c];
#pragma unroll
        for (int o = 16; o; o >>= 1) p += __shfl_xor_sync(0xffffffffu, p, o);
        if (lane == 0) sc[12 + wid] = p + b_af[0];
    }
    __syncthreads();
    if (tid == 0) {
        float s0 = sc[12], s1 = sc[13];
        float mx = fmaxf(s0, s1);
        float e0 = expf(s0 - mx), e1 = expf(s1 - mx);
        float inv = 1.f / (e0 + e1);
        fw[0] = e0 * inv; fw[1] = e1 * inv;
    }
    __syncthreads();
    fused[tid] = fw[0] * y2[0][tid] + fw[1] * y2[1][tid];
    __syncthreads();
    {
        float acc = b_fc[tid];
        for (int k = 0; k < 256; k++) acc += fused[k] * W_fc[k * 256 + tid];
        out[tid] = acc;
    }
}

// ---------------------------------------------------------------------------
extern "C" void kernel_launch(void* const* d_in, const int* in_sizes, int n_in,
                              void* d_out, int out_size)
{
    const float* audio = (const float*)d_in[0];
    const float* text  = (const float*)d_in[1];
    const float* W_pa  = (const float*)d_in[2];
    const float* b_pa  = (const float*)d_in[3];
    const float* W_pt  = (const float*)d_in[4];
    const float* b_pt  = (const float*)d_in[5];
    const float* W_g1  = (const float*)d_in[6];
    const float* as1   = (const float*)d_in[7];
    const float* ad1   = (const float*)d_in[8];
    const float* b_g1  = (const float*)d_in[9];
    const float* W_g2  = (const float*)d_in[10];
    const float* as2   = (const float*)d_in[11];
    const float* ad2   = (const float*)d_in[12];
    const float* b_g2  = (const float*)d_in[13];
    const float* W_af  = (const float*)d_in[14];
    const float* b_af  = (const float*)d_in[15];
    const float* W_fc  = (const float*)d_in[16];
    const float* b_fc  = (const float*)d_in[17];
    float* out = (float*)d_out;

    const int batch = in_sizes[0] / H;           // 65536
    const int grid  = batch / MB;                // 2048

    cudaFuncSetAttribute(fused_main, cudaFuncAttributeMaxDynamicSharedMemorySize,
                         SMEM_BYTES);

    fused_main<<<grid, NTHR, SMEM_BYTES>>>(
        audio, text, W_pa, b_pa, W_pt, b_pt, W_g1, b_g1, W_g2, b_g2,
        W_af, b_af, W_fc, b_fc, out);

    fix_batch0<<<1, 256>>>(
        audio, text, W_pa, b_pa, W_pt, b_pt, W_g1, as1, ad1, b_g1,
        W_g2, as2, ad2, b_g2, W_af, b_af, W_fc, b_fc, out);
}